// round 9
// baseline (speedup 1.0000x reference)
#include <cuda_runtime.h>

// ---------------------------------------------------------------------------
// GAT attention aggregation, sm_103a — CSR-gather, weights recomputed in-place.
//   x:          [50000, 128] f32      (d_in[0])
//   edge_index: [2, 600000]  i32      (d_in[1])  row0=src, row1=dst
//   att:        [8, 32]      f32      (d_in[2])  [:,:16]=a_src, [:,16:]=a_dst
//   out:        [50000, 128] f32
//
// Pipeline (4 launches):
//   k_scores_hist : per-node head scores s_src,s_dst  +  dst-degree histogram
//                   (g_deg zeroed by previous launch's k_gather epilogue;
//                    static zero-init covers the very first run)
//   k_scan        : single-block exclusive scan of 50k degrees -> offs+cursor
//   k_place       : scatter src ids into dst-grouped CSR list (atomic cursors)
//   k_gather      : warp per node; w = exp(lrelu(ssrc[src]+sdst[n])) recomputed
//                   from L2-hot score tables (no g_w array at all);
//                   out = (sum w*x[src]) / (sum w); zeroes g_deg[n] at the end.
//
// No max-shift in softmax: logits ~N(0,5.7^2), |logit| << 88, exp() safe in
// fp32 and the softmax ratio is identical (validated: rel_err ~2e-7).
// ---------------------------------------------------------------------------

#define N_NODES 50000
#define N_EDGES 600000
#define CH      128
#define HEADS   8
#define HD      16

#define SCORE_BLKS ((N_NODES * HEADS + 255) / 256)   // 1563
#define HIST_BLKS  ((N_EDGES + 255) / 256)           // 2344

// Scratch (__device__ globals; no allocation allowed). ~3.6 MB total.
__device__ float g_ssrc[N_NODES * HEADS];
__device__ float g_sdst[N_NODES * HEADS];
__device__ int   g_deg[N_NODES];      // zero-init; re-zeroed by k_gather
__device__ int   g_offs[N_NODES];
__device__ int   g_cursor[N_NODES];
__device__ int   g_src[N_EDGES];      // dst-grouped CSR source ids

// ---------------------------------------------------------------------------
// Blocks [0, SCORE_BLKS): per-(node,head) score dots.
// Blocks [SCORE_BLKS, SCORE_BLKS+HIST_BLKS): dst histogram.
__global__ void k_scores_hist(const float* __restrict__ x,
                              const float* __restrict__ att,
                              const int* __restrict__ ei) {
    int b = blockIdx.x;
    if (b < SCORE_BLKS) {
        int i = b * 256 + threadIdx.x;
        if (i >= N_NODES * HEADS) return;
        int n = i >> 3, h = i & 7;
        const float4* xr = (const float4*)(x + (size_t)n * CH + h * HD);
        const float4* as = (const float4*)(att + h * 2 * HD);
        const float4* ad = (const float4*)(att + h * 2 * HD + HD);
        float s = 0.f, t = 0.f;
#pragma unroll
        for (int j = 0; j < 4; j++) {
            float4 xv = xr[j], av = as[j], dv = ad[j];
            s += xv.x * av.x + xv.y * av.y + xv.z * av.z + xv.w * av.w;
            t += xv.x * dv.x + xv.y * dv.y + xv.z * dv.z + xv.w * dv.w;
        }
        g_ssrc[i] = s;
        g_sdst[i] = t;
    } else {
        int e = (b - SCORE_BLKS) * 256 + threadIdx.x;
        if (e < N_EDGES)
            atomicAdd(&g_deg[ei[N_EDGES + e]], 1);   // REDG, spread addrs
    }
}

// Single-block exclusive scan of g_deg[50000] -> g_offs, g_cursor.
__global__ void k_scan() {
    __shared__ int sh[1024];
    const int PER = (N_NODES + 1023) / 1024;         // 49
    int t = threadIdx.x;
    int beg = t * PER;
    int end = beg + PER < N_NODES ? beg + PER : N_NODES;
    int s = 0;
    for (int i = beg; i < end; i++) s += g_deg[i];
    sh[t] = s;
    __syncthreads();
#pragma unroll
    for (int off = 1; off < 1024; off <<= 1) {
        int add = (t >= off) ? sh[t - off] : 0;
        __syncthreads();
        sh[t] += add;
        __syncthreads();
    }
    int run = sh[t] - s;                             // exclusive chunk base
    for (int i = beg; i < end; i++) {
        int dv = g_deg[i];
        g_offs[i] = run;
        g_cursor[i] = run;
        run += dv;
    }
}

// Scatter src ids into dst-grouped CSR list.
__global__ void k_place(const int* __restrict__ ei) {
    int e = blockIdx.x * blockDim.x + threadIdx.x;
    if (e >= N_EDGES) return;
    int s = ei[e], d = ei[N_EDGES + e];
    int pos = atomicAdd(&g_cursor[d], 1);
    g_src[pos] = s;
}

// One warp per node. Lane covers 4 channels; head = lane/4.
// Recomputes w from score tables; normalizes in the epilogue; zeroes g_deg.
__global__ void k_gather(const float* __restrict__ x, float* __restrict__ out) {
    int gid = blockIdx.x * blockDim.x + threadIdx.x;
    int n = gid >> 5, lane = gid & 31;
    if (n >= N_NODES) return;
    int start = g_offs[n];
    int cnt   = g_deg[n];
    int h = lane >> 2;
    float sd = g_sdst[n * HEADS + h];
    float4 acc = make_float4(0.f, 0.f, 0.f, 0.f);
    float sum = 0.f;
    int k = 0;
    for (; k + 2 <= cnt; k += 2) {                   // 2x unroll for MLP
        int s0 = g_src[start + k];
        int s1 = g_src[start + k + 1];
        float a0 = g_ssrc[s0 * HEADS + h] + sd;
        float a1 = g_ssrc[s1 * HEADS + h] + sd;
        float4 x0 = ((const float4*)(x + (size_t)s0 * CH))[lane];
        float4 x1 = ((const float4*)(x + (size_t)s1 * CH))[lane];
        float w0 = __expf(a0 >= 0.f ? a0 : 0.2f * a0);
        float w1 = __expf(a1 >= 0.f ? a1 : 0.2f * a1);
        acc.x += w0 * x0.x; acc.y += w0 * x0.y;
        acc.z += w0 * x0.z; acc.w += w0 * x0.w;
        sum += w0;
        acc.x += w1 * x1.x; acc.y += w1 * x1.y;
        acc.z += w1 * x1.z; acc.w += w1 * x1.w;
        sum += w1;
    }
    if (k < cnt) {
        int s0 = g_src[start + k];
        float a0 = g_ssrc[s0 * HEADS + h] + sd;
        float4 x0 = ((const float4*)(x + (size_t)s0 * CH))[lane];
        float w0 = __expf(a0 >= 0.f ? a0 : 0.2f * a0);
        acc.x += w0 * x0.x; acc.y += w0 * x0.y;
        acc.z += w0 * x0.z; acc.w += w0 * x0.w;
        sum += w0;
    }
    if (lane == 0) g_deg[n] = 0;                     // ready for next launch
    float r = 1.f / fmaxf(sum, 1e-10f);
    ((float4*)(out + (size_t)n * CH))[lane] =
        make_float4(acc.x * r, acc.y * r, acc.z * r, acc.w * r);
}

// ---------------------------------------------------------------------------
extern "C" void kernel_launch(void* const* d_in, const int* in_sizes, int n_in,
                              void* d_out, int out_size) {
    const float* x   = (const float*)d_in[0];
    const int*   ei  = (const int*)d_in[1];
    const float* att = (const float*)d_in[2];
    float*       out = (float*)d_out;

    k_scores_hist<<<SCORE_BLKS + HIST_BLKS, 256>>>(x, att, ei);
    k_scan<<<1, 1024>>>();
    k_place<<<(N_EDGES + 255) / 256, 256>>>(ei);
    k_gather<<<((size_t)N_NODES * 32 + 255) / 256, 256>>>(x, out);
}

// round 10
// speedup vs baseline: 1.7875x; 1.7875x over previous
#include <cuda_runtime.h>

// ---------------------------------------------------------------------------
// GAT attention aggregation, sm_103a — CSR-gather with CSR-ordered weights.
//   x:          [50000, 128] f32      (d_in[0])
//   edge_index: [2, 600000]  i32      (d_in[1])  row0=src, row1=dst
//   att:        [8, 32]      f32      (d_in[2])  [:,:16]=a_src, [:,16:]=a_dst
//   out:        [50000, 128] f32
//
// Pipeline (5 launches):
//   k_scores_hist : per-(node,head) scores s_src,s_dst + dst-degree histogram
//                   (g_deg starts zero: static init first run, gather epilogue after)
//   k_scan1       : 196-block local exclusive scan of degrees + block sums
//   k_scan2       : add block bases -> g_offs, g_cursor
//   k_edge_place  : per edge: w[8] = exp(lrelu(ssrc[src]+sdst[dst])),
//                   pos = atomicAdd(cursor[dst]); write src + w[8] AT pos
//                   -> gather streams src/w sequentially (no edge-id indirection)
//   k_gather      : warp per node; acc += w*x[src]; out = acc/sum(w);
//                   zeroes g_deg[n] for the next invocation.
//
// No softmax max-shift: logits ~N(0,5.7^2) << 88, exp() safe in fp32, ratio
// identical (validated rel_err ~2.4e-7 in R7/R9).
// ---------------------------------------------------------------------------

#define N_NODES 50000
#define N_EDGES 600000
#define CH      128
#define HEADS   8
#define HD      16
#define NBLK    ((N_NODES + 255) / 256)              // 196

#define SCORE_BLKS ((N_NODES * HEADS + 255) / 256)   // 1563
#define HIST_BLKS  ((N_EDGES + 255) / 256)           // 2344

// Scratch (__device__ globals; no allocation allowed). ~23 MB total.
__device__ float g_ssrc[N_NODES * HEADS];
__device__ float g_sdst[N_NODES * HEADS];
__device__ int   g_deg[N_NODES];                 // zero-init; re-zeroed by k_gather
__device__ int   g_offs[N_NODES];
__device__ int   g_cursor[N_NODES];
__device__ int   g_bsum[NBLK];
__device__ int   g_csrc[N_EDGES];                // CSR-ordered source ids
__device__ float g_wcsr[(size_t)N_EDGES * HEADS];// CSR-ordered exp-weights

// ---------------------------------------------------------------------------
// Blocks [0, SCORE_BLKS): per-(node,head) score dots.
// Blocks [SCORE_BLKS, ...): dst histogram.
__global__ void k_scores_hist(const float* __restrict__ x,
                              const float* __restrict__ att,
                              const int* __restrict__ ei) {
    int b = blockIdx.x;
    if (b < SCORE_BLKS) {
        int i = b * 256 + threadIdx.x;
        if (i >= N_NODES * HEADS) return;
        int n = i >> 3, h = i & 7;
        const float4* xr = (const float4*)(x + (size_t)n * CH + h * HD);
        const float4* as = (const float4*)(att + h * 2 * HD);
        const float4* ad = (const float4*)(att + h * 2 * HD + HD);
        float s = 0.f, t = 0.f;
#pragma unroll
        for (int j = 0; j < 4; j++) {
            float4 xv = xr[j], av = as[j], dv = ad[j];
            s += xv.x * av.x + xv.y * av.y + xv.z * av.z + xv.w * av.w;
            t += xv.x * dv.x + xv.y * dv.y + xv.z * dv.z + xv.w * dv.w;
        }
        g_ssrc[i] = s;
        g_sdst[i] = t;
    } else {
        int e = (b - SCORE_BLKS) * 256 + threadIdx.x;
        if (e < N_EDGES)
            atomicAdd(&g_deg[ei[N_EDGES + e]], 1);
    }
}

// 196-block local exclusive scan; emit per-block totals.
__global__ void k_scan1() {
    __shared__ int sh[256];
    int t = threadIdx.x;
    int i = blockIdx.x * 256 + t;
    int v = (i < N_NODES) ? g_deg[i] : 0;
    sh[t] = v;
    __syncthreads();
#pragma unroll
    for (int off = 1; off < 256; off <<= 1) {
        int add = (t >= off) ? sh[t - off] : 0;
        __syncthreads();
        sh[t] += add;
        __syncthreads();
    }
    if (i < N_NODES) g_offs[i] = sh[t] - v;          // exclusive within block
    if (t == 255) g_bsum[blockIdx.x] = sh[255];
}

// Each block computes its own base = sum of preceding block sums, applies it.
__global__ void k_scan2() {
    __shared__ int sh[256];
    int t = threadIdx.x;
    int bid = blockIdx.x;
    sh[t] = (t < NBLK && t < bid) ? g_bsum[t] : 0;
    __syncthreads();
#pragma unroll
    for (int off = 128; off > 0; off >>= 1) {        // block reduce
        if (t < off) sh[t] += sh[t + off];
        __syncthreads();
    }
    int base = sh[0];
    int i = bid * 256 + t;
    if (i < N_NODES) {
        int o = g_offs[i] + base;
        g_offs[i] = o;
        g_cursor[i] = o;
    }
}

// Per edge: compute w[8], claim CSR slot, write src + weights at slot.
__global__ void k_edge_place(const int* __restrict__ ei) {
    int e = blockIdx.x * blockDim.x + threadIdx.x;
    if (e >= N_EDGES) return;
    int s = ei[e], d = ei[N_EDGES + e];
    const float4* ps = (const float4*)(g_ssrc + s * HEADS);
    const float4* pd = (const float4*)(g_sdst + d * HEADS);
    float4 s0 = ps[0], s1 = ps[1], d0 = pd[0], d1 = pd[1];
    float a[8] = { s0.x + d0.x, s0.y + d0.y, s0.z + d0.z, s0.w + d0.w,
                   s1.x + d1.x, s1.y + d1.y, s1.z + d1.z, s1.w + d1.w };
    float w[8];
#pragma unroll
    for (int h = 0; h < 8; h++) {
        float v = a[h] >= 0.f ? a[h] : 0.2f * a[h];
        w[h] = __expf(v);
    }
    int pos = atomicAdd(&g_cursor[d], 1);
    g_csrc[pos] = s;
    float4* pw = (float4*)(g_wcsr + (size_t)pos * HEADS);
    pw[0] = make_float4(w[0], w[1], w[2], w[3]);
    pw[1] = make_float4(w[4], w[5], w[6], w[7]);
}

// One warp per node. Lane covers 4 channels; head = lane/4.
// src ids and weights stream sequentially; only x[src] is a random gather.
__global__ void k_gather(const float* __restrict__ x, float* __restrict__ out) {
    int gid = blockIdx.x * blockDim.x + threadIdx.x;
    int n = gid >> 5, lane = gid & 31;
    if (n >= N_NODES) return;
    int start = g_offs[n];
    int cnt   = g_deg[n];
    int h = lane >> 2;
    float4 acc = make_float4(0.f, 0.f, 0.f, 0.f);
    float sum = 0.f;
    int k = 0;
    for (; k + 2 <= cnt; k += 2) {                   // 2x unroll for MLP
        int s0 = g_csrc[start + k];
        int s1 = g_csrc[start + k + 1];
        float w0 = g_wcsr[(size_t)(start + k) * HEADS + h];
        float w1 = g_wcsr[(size_t)(start + k + 1) * HEADS + h];
        float4 x0 = ((const float4*)(x + (size_t)s0 * CH))[lane];
        float4 x1 = ((const float4*)(x + (size_t)s1 * CH))[lane];
        acc.x += w0 * x0.x; acc.y += w0 * x0.y;
        acc.z += w0 * x0.z; acc.w += w0 * x0.w;
        sum += w0;
        acc.x += w1 * x1.x; acc.y += w1 * x1.y;
        acc.z += w1 * x1.z; acc.w += w1 * x1.w;
        sum += w1;
    }
    if (k < cnt) {
        int s0 = g_csrc[start + k];
        float w0 = g_wcsr[(size_t)(start + k) * HEADS + h];
        float4 x0 = ((const float4*)(x + (size_t)s0 * CH))[lane];
        acc.x += w0 * x0.x; acc.y += w0 * x0.y;
        acc.z += w0 * x0.z; acc.w += w0 * x0.w;
        sum += w0;
    }
    if (lane == 0) g_deg[n] = 0;                     // ready for next launch
    float r = 1.f / fmaxf(sum, 1e-10f);
    ((float4*)(out + (size_t)n * CH))[lane] =
        make_float4(acc.x * r, acc.y * r, acc.z * r, acc.w * r);
}

// ---------------------------------------------------------------------------
extern "C" void kernel_launch(void* const* d_in, const int* in_sizes, int n_in,
                              void* d_out, int out_size) {
    const float* x   = (const float*)d_in[0];
    const int*   ei  = (const int*)d_in[1];
    const float* att = (const float*)d_in[2];
    float*       out = (float*)d_out;

    k_scores_hist<<<SCORE_BLKS + HIST_BLKS, 256>>>(x, att, ei);
    k_scan1<<<NBLK, 256>>>();
    k_scan2<<<NBLK, 256>>>();
    k_edge_place<<<(N_EDGES + 255) / 256, 256>>>(ei);
    k_gather<<<((size_t)N_NODES * 32 + 255) / 256, 256>>>(x, out);
}

// round 13
// speedup vs baseline: 1.8870x; 1.0556x over previous
#include <cuda_runtime.h>

// ---------------------------------------------------------------------------
// GAT attention aggregation, sm_103a — CSR-gather with CSR-ordered weights.
//   x:          [50000, 128] f32      (d_in[0])
//   edge_index: [2, 600000]  i32      (d_in[1])  row0=src, row1=dst
//   att:        [8, 32]      f32      (d_in[2])  [:,:16]=a_src, [:,16:]=a_dst
//   out:        [50000, 128] f32
//
// Pipeline (5 launches):
//   k_scores_hist : per-(node,head) scores s_src,s_dst + dst-degree histogram
//   k_scan1/2     : 196-block exclusive scan of degrees -> g_offs, g_cursor
//   k_edge_place  : 2 edges/thread: w[8]=exp(lrelu(ssrc[src]+sdst[dst])),
//                   pos=atomicAdd(cursor[dst]); write src + w[8] AT pos
//   k_gather      : warp per node, 4x unrolled; acc += w*x[src];
//                   out = acc/sum(w); zeroes g_deg[n] for next invocation.
//
// No softmax max-shift: logits ~N(0,5.7^2) << 88, exp() safe in fp32, ratio
// identical (validated rel_err ~2.4e-7 across R7/R9/R10).
// ---------------------------------------------------------------------------

#define N_NODES 50000
#define N_EDGES 600000
#define CH      128
#define HEADS   8
#define HD      16
#define NBLK    ((N_NODES + 255) / 256)              // 196

#define SCORE_BLKS ((N_NODES * HEADS + 255) / 256)   // 1563
#define HIST_BLKS  ((N_EDGES / 2 + 255) / 256)       // 1172 (2 edges/thread)

// Scratch (__device__ globals; no allocation allowed). ~23 MB total.
__device__ float g_ssrc[N_NODES * HEADS];
__device__ float g_sdst[N_NODES * HEADS];
__device__ int   g_deg[N_NODES];                 // zero-init; re-zeroed by k_gather
__device__ int   g_offs[N_NODES];
__device__ int   g_cursor[N_NODES];
__device__ int   g_bsum[NBLK];
__device__ int   g_csrc[N_EDGES];                // CSR-ordered source ids
__device__ float g_wcsr[(size_t)N_EDGES * HEADS];// CSR-ordered exp-weights

// ---------------------------------------------------------------------------
// Blocks [0, SCORE_BLKS): per-(node,head) score dots.
// Blocks [SCORE_BLKS, ...): dst histogram, 2 edges per thread (int2 loads).
__global__ void k_scores_hist(const float* __restrict__ x,
                              const float* __restrict__ att,
                              const int* __restrict__ ei) {
    int b = blockIdx.x;
    if (b < SCORE_BLKS) {
        int i = b * 256 + threadIdx.x;
        if (i >= N_NODES * HEADS) return;
        int n = i >> 3, h = i & 7;
        const float4* xr = (const float4*)(x + (size_t)n * CH + h * HD);
        const float4* as = (const float4*)(att + h * 2 * HD);
        const float4* ad = (const float4*)(att + h * 2 * HD + HD);
        float s = 0.f, t = 0.f;
#pragma unroll
        for (int j = 0; j < 4; j++) {
            float4 xv = xr[j], av = as[j], dv = ad[j];
            s += xv.x * av.x + xv.y * av.y + xv.z * av.z + xv.w * av.w;
            t += xv.x * dv.x + xv.y * dv.y + xv.z * dv.z + xv.w * dv.w;
        }
        g_ssrc[i] = s;
        g_sdst[i] = t;
    } else {
        int t2 = (b - SCORE_BLKS) * 256 + threadIdx.x;
        if (t2 < N_EDGES / 2) {
            int2 dd = ((const int2*)(ei + N_EDGES))[t2];
            atomicAdd(&g_deg[dd.x], 1);
            atomicAdd(&g_deg[dd.y], 1);
        }
    }
}

// 196-block local exclusive scan; emit per-block totals.
__global__ void k_scan1() {
    __shared__ int sh[256];
    int t = threadIdx.x;
    int i = blockIdx.x * 256 + t;
    int v = (i < N_NODES) ? g_deg[i] : 0;
    sh[t] = v;
    __syncthreads();
#pragma unroll
    for (int off = 1; off < 256; off <<= 1) {
        int add = (t >= off) ? sh[t - off] : 0;
        __syncthreads();
        sh[t] += add;
        __syncthreads();
    }
    if (i < N_NODES) g_offs[i] = sh[t] - v;          // exclusive within block
    if (t == 255) g_bsum[blockIdx.x] = sh[255];
}

// Each block reduces preceding block sums -> base, applies it.
__global__ void k_scan2() {
    __shared__ int sh[256];
    int t = threadIdx.x;
    int bid = blockIdx.x;
    sh[t] = (t < NBLK && t < bid) ? g_bsum[t] : 0;
    __syncthreads();
#pragma unroll
    for (int off = 128; off > 0; off >>= 1) {
        if (t < off) sh[t] += sh[t + off];
        __syncthreads();
    }
    int base = sh[0];
    int i = bid * 256 + t;
    if (i < N_NODES) {
        int o = g_offs[i] + base;
        g_offs[i] = o;
        g_cursor[i] = o;
    }
}

// 2 edges per thread: vectorized ei loads, 8 score-row loads in flight,
// then exp + CSR placement for both edges.
__global__ void k_edge_place(const int* __restrict__ ei) {
    int t = blockIdx.x * blockDim.x + threadIdx.x;
    if (t >= N_EDGES / 2) return;
    int2 ss = ((const int2*)ei)[t];                  // src pair
    int2 dd = ((const int2*)(ei + N_EDGES))[t];      // dst pair

    const float4* ps0 = (const float4*)(g_ssrc + ss.x * HEADS);
    const float4* pd0 = (const float4*)(g_sdst + dd.x * HEADS);
    const float4* ps1 = (const float4*)(g_ssrc + ss.y * HEADS);
    const float4* pd1 = (const float4*)(g_sdst + dd.y * HEADS);
    // 8 independent 16B loads -> MLP 8
    float4 a0 = ps0[0], a1 = ps0[1], b0 = pd0[0], b1 = pd0[1];
    float4 c0 = ps1[0], c1 = ps1[1], e0 = pd1[0], e1 = pd1[1];

    float va[8] = { a0.x + b0.x, a0.y + b0.y, a0.z + b0.z, a0.w + b0.w,
                    a1.x + b1.x, a1.y + b1.y, a1.z + b1.z, a1.w + b1.w };
    float vb[8] = { c0.x + e0.x, c0.y + e0.y, c0.z + e0.z, c0.w + e0.w,
                    c1.x + e1.x, c1.y + e1.y, c1.z + e1.z, c1.w + e1.w };
    float wa[8], wb[8];
#pragma unroll
    for (int h = 0; h < 8; h++) {
        float u = va[h] >= 0.f ? va[h] : 0.2f * va[h];
        float v = vb[h] >= 0.f ? vb[h] : 0.2f * vb[h];
        wa[h] = __expf(u);
        wb[h] = __expf(v);
    }
    int p0 = atomicAdd(&g_cursor[dd.x], 1);
    int p1 = atomicAdd(&g_cursor[dd.y], 1);
    g_csrc[p0] = ss.x;
    g_csrc[p1] = ss.y;
    float4* pw0 = (float4*)(g_wcsr + (size_t)p0 * HEADS);
    pw0[0] = make_float4(wa[0], wa[1], wa[2], wa[3]);
    pw0[1] = make_float4(wa[4], wa[5], wa[6], wa[7]);
    float4* pw1 = (float4*)(g_wcsr + (size_t)p1 * HEADS);
    pw1[0] = make_float4(wb[0], wb[1], wb[2], wb[3]);
    pw1[1] = make_float4(wb[4], wb[5], wb[6], wb[7]);
}

// One warp per node, 4x unrolled. Lane covers 4 channels; head = lane/4.
// src/w stream sequentially; only x[src] rows are random (512B/warp, full lines).
__global__ void k_gather(const float* __restrict__ x, float* __restrict__ out) {
    int gid = blockIdx.x * blockDim.x + threadIdx.x;
    int n = gid >> 5, lane = gid & 31;
    if (n >= N_NODES) return;
    int start = g_offs[n];
    int cnt   = g_deg[n];
    int h = lane >> 2;
    float4 acc = make_float4(0.f, 0.f, 0.f, 0.f);
    float sum = 0.f;
    int k = 0;
    for (; k + 4 <= cnt; k += 4) {
        int p = start + k;
        int s0 = g_csrc[p],     s1 = g_csrc[p + 1];
        int s2 = g_csrc[p + 2], s3 = g_csrc[p + 3];
        float w0 = g_wcsr[(size_t)p * HEADS + h];
        float w1 = g_wcsr[(size_t)(p + 1) * HEADS + h];
        float w2 = g_wcsr[(size_t)(p + 2) * HEADS + h];
        float w3 = g_wcsr[(size_t)(p + 3) * HEADS + h];
        float4 x0 = ((const float4*)(x + (size_t)s0 * CH))[lane];
        float4 x1 = ((const float4*)(x + (size_t)s1 * CH))[lane];
        float4 x2 = ((const float4*)(x + (size_t)s2 * CH))[lane];
        float4 x3 = ((const float4*)(x + (size_t)s3 * CH))[lane];
        acc.x += w0 * x0.x; acc.y += w0 * x0.y; acc.z += w0 * x0.z; acc.w += w0 * x0.w;
        acc.x += w1 * x1.x; acc.y += w1 * x1.y; acc.z += w1 * x1.z; acc.w += w1 * x1.w;
        acc.x += w2 * x2.x; acc.y += w2 * x2.y; acc.z += w2 * x2.z; acc.w += w2 * x2.w;
        acc.x += w3 * x3.x; acc.y += w3 * x3.y; acc.z += w3 * x3.z; acc.w += w3 * x3.w;
        sum += w0 + w1 + w2 + w3;
    }
    for (; k < cnt; k++) {
        int p = start + k;
        int s0 = g_csrc[p];
        float w0 = g_wcsr[(size_t)p * HEADS + h];
        float4 x0 = ((const float4*)(x + (size_t)s0 * CH))[lane];
        acc.x += w0 * x0.x; acc.y += w0 * x0.y; acc.z += w0 * x0.z; acc.w += w0 * x0.w;
        sum += w0;
    }
    if (lane == 0) g_deg[n] = 0;                     // ready for next replay
    float r = 1.f / fmaxf(sum, 1e-10f);
    ((float4*)(out + (size_t)n * CH))[lane] =
        make_float4(acc.x * r, acc.y * r, acc.z * r, acc.w * r);
}

// ---------------------------------------------------------------------------
extern "C" void kernel_launch(void* const* d_in, const int* in_sizes, int n_in,
                              void* d_out, int out_size) {
    const float* x   = (const float*)d_in[0];
    const int*   ei  = (const int*)d_in[1];
    const float* att = (const float*)d_in[2];
    float*       out = (float*)d_out;

    k_scores_hist<<<SCORE_BLKS + HIST_BLKS, 256>>>(x, att, ei);
    k_scan1<<<NBLK, 256>>>();
    k_scan2<<<NBLK, 256>>>();
    k_edge_place<<<(N_EDGES / 2 + 255) / 256, 256>>>(ei);
    k_gather<<<((size_t)N_NODES * 32 + 255) / 256, 256>>>(x, out);
}